// round 1
// baseline (speedup 1.0000x reference)
#include <cuda_runtime.h>
#include <cuda_bf16.h>

#define LN_EPS 1e-5f

static __device__ __forceinline__ float warp_sum(float v) {
#pragma unroll
    for (int o = 16; o; o >>= 1) v += __shfl_xor_sync(0xffffffffu, v, o);
    return v;
}

// One block per output row (b, t). Fused: select source row (cv vs ocr),
// LayerNorm it, LayerNorm (pos_emb[t] + type_emb[type]), sum, write out.
__global__ void __launch_bounds__(192)
prev_embedding_kernel(
    const float* __restrict__ cv,    // [V, H]
    const float* __restrict__ ocr,   // [B, N, H]
    const int*   __restrict__ ids,   // [B, T]  (int32 — jax demotes int64)
    const float* __restrict__ cvg, const float* __restrict__ cvb,
    const float* __restrict__ og,  const float* __restrict__ ob,
    const float* __restrict__ pos,   // [T, H]
    const float* __restrict__ typ,   // [2, H]
    const float* __restrict__ eg,  const float* __restrict__ eb,
    float* __restrict__ out,         // [B, T, H]
    int V, int N, int T, int H)
{
    const int bt = blockIdx.x;
    const int b = bt / T;
    const int t = bt - b * T;

    const int id = ids[bt];
    const float* src;
    const float* gam;
    const float* bet;
    if (id >= V) {
        int oi = id - V;
        oi = max(0, min(oi, N - 1));
        src = ocr + ((size_t)b * (size_t)N + (size_t)oi) * (size_t)H;
        gam = og; bet = ob;
    } else {
        int ci = max(0, min(id, V - 1));
        src = cv + (size_t)ci * (size_t)H;
        gam = cvg; bet = cvb;
    }

    const float* prow = pos + (size_t)t * (size_t)H;
    const float* trow = typ + ((t >= V) ? (size_t)H : (size_t)0);

    const int H4   = H >> 2;
    const int tid  = threadIdx.x;
    const int nthr = blockDim.x;

    // --- joint single-pass reduction: sum/sumsq of gathered row and pos+type row
    float sa = 0.f, ssa = 0.f, sp = 0.f, ssp = 0.f;
    for (int i = tid; i < H4; i += nthr) {
        float4 a  = ((const float4*)src)[i];
        float4 pp = ((const float4*)prow)[i];
        float4 tt = ((const float4*)trow)[i];
        float px = pp.x + tt.x, py = pp.y + tt.y, pz = pp.z + tt.z, pw = pp.w + tt.w;
        sa  += a.x + a.y + a.z + a.w;
        ssa += a.x * a.x + a.y * a.y + a.z * a.z + a.w * a.w;
        sp  += px + py + pz + pw;
        ssp += px * px + py * py + pz * pz + pw * pw;
    }

    __shared__ float red[8][4];
    const int lane = tid & 31;
    const int w    = tid >> 5;
    sa = warp_sum(sa); ssa = warp_sum(ssa); sp = warp_sum(sp); ssp = warp_sum(ssp);
    if (lane == 0) { red[w][0] = sa; red[w][1] = ssa; red[w][2] = sp; red[w][3] = ssp; }
    __syncthreads();
    const int nw = (nthr + 31) >> 5;
    if (tid == 0) {
        float a0 = 0.f, a1 = 0.f, a2 = 0.f, a3 = 0.f;
        for (int i = 0; i < nw; i++) {
            a0 += red[i][0]; a1 += red[i][1]; a2 += red[i][2]; a3 += red[i][3];
        }
        red[0][0] = a0; red[0][1] = a1; red[0][2] = a2; red[0][3] = a3;
    }
    __syncthreads();

    const float invH = 1.0f / (float)H;
    const float mua = red[0][0] * invH;
    const float va  = red[0][1] * invH - mua * mua;
    const float mup = red[0][2] * invH;
    const float vp  = red[0][3] * invH - mup * mup;
    const float ra  = rsqrtf(va + LN_EPS);
    const float rp  = rsqrtf(vp + LN_EPS);

    // --- epilogue: second pass re-reads hit L1; fused write
    float4* o4 = (float4*)(out + (size_t)bt * (size_t)H);
    for (int i = tid; i < H4; i += nthr) {
        float4 a   = ((const float4*)src)[i];
        float4 pp  = ((const float4*)prow)[i];
        float4 tt  = ((const float4*)trow)[i];
        float4 g4  = ((const float4*)gam)[i];
        float4 b4  = ((const float4*)bet)[i];
        float4 eg4 = ((const float4*)eg)[i];
        float4 eb4 = ((const float4*)eb)[i];
        float4 r;
        r.x = (a.x - mua) * ra * g4.x + b4.x + ((pp.x + tt.x) - mup) * rp * eg4.x + eb4.x;
        r.y = (a.y - mua) * ra * g4.y + b4.y + ((pp.y + tt.y) - mup) * rp * eg4.y + eb4.y;
        r.z = (a.z - mua) * ra * g4.z + b4.z + ((pp.z + tt.z) - mup) * rp * eg4.z + eb4.z;
        r.w = (a.w - mua) * ra * g4.w + b4.w + ((pp.w + tt.w) - mup) * rp * eg4.w + eb4.w;
        o4[i] = r;
    }
}

extern "C" void kernel_launch(void* const* d_in, const int* in_sizes, int n_in,
                              void* d_out, int out_size) {
    // metadata order:
    // 0 common_voc_embed [V,H] f32
    // 1 ocr_embed        [B,N,H] f32
    // 2 prev_ids         [B,T] int (int32 after jax x64-demotion)
    // 3 cv_gamma [H]  4 cv_beta [H]
    // 5 ocr_gamma [H] 6 ocr_beta [H]
    // 7 pos_emb [T,H]
    // 8 type_emb [2,H]
    // 9 emb_gamma [H] 10 emb_beta [H]
    const float* cv  = (const float*)d_in[0];
    const float* ocr = (const float*)d_in[1];
    const int*   ids = (const int*)d_in[2];
    const float* cvg = (const float*)d_in[3];
    const float* cvb = (const float*)d_in[4];
    const float* og  = (const float*)d_in[5];
    const float* ob  = (const float*)d_in[6];
    const float* pos = (const float*)d_in[7];
    const float* typ = (const float*)d_in[8];
    const float* eg  = (const float*)d_in[9];
    const float* eb  = (const float*)d_in[10];
    float* out = (float*)d_out;

    const int H  = in_sizes[3];
    const int V  = in_sizes[0] / H;
    const int T  = in_sizes[7] / H;
    const int BT = in_sizes[2];       // B * T
    const int B  = BT / T;
    const int N  = in_sizes[1] / (B * H);

    // H=768 -> H/4=192 float4 lanes; one float4 per thread.
    int threads = H >> 2;
    if (threads > 256) threads = 256;
    if (threads < 32)  threads = 32;

    prev_embedding_kernel<<<BT, threads>>>(cv, ocr, ids, cvg, cvb, og, ob,
                                           pos, typ, eg, eb, out, V, N, T, H);
}

// round 3
// speedup vs baseline: 1.2574x; 1.2574x over previous
#include <cuda_runtime.h>
#include <cuda_bf16.h>

#define LN_EPS 1e-5f
#define WARPS_PER_BLOCK 8

static __device__ __forceinline__ float warp_sum(float v) {
#pragma unroll
    for (int o = 16; o; o >>= 1) v += __shfl_xor_sync(0xffffffffu, v, o);
    return v;
}

// One WARP per output row (b, t). Row (H=768 floats) is register-cached:
// 6 float4 per lane for the gathered row + 6 for pos+type. Shuffle-only
// reduction, no shared memory, no __syncthreads, single global read pass.
__global__ void __launch_bounds__(WARPS_PER_BLOCK * 32)
prev_embedding_kernel(
    const float* __restrict__ cv,    // [V, H]
    const float* __restrict__ ocr,   // [B, N, H]
    const int*   __restrict__ ids,   // [B, T]
    const float* __restrict__ cvg, const float* __restrict__ cvb,
    const float* __restrict__ og,  const float* __restrict__ ob,
    const float* __restrict__ pos,   // [T, H]
    const float* __restrict__ typ,   // [2, H]
    const float* __restrict__ eg,  const float* __restrict__ eb,
    float* __restrict__ out,         // [B, T, H]
    int V, int N, int T, int H, int BT)
{
    const int wrow = blockIdx.x * WARPS_PER_BLOCK + (threadIdx.x >> 5);
    if (wrow >= BT) return;
    const int lane = threadIdx.x & 31;

    const int b = wrow / T;
    const int t = wrow - b * T;

    const int id = __ldg(ids + wrow);
    const float* src;
    const float* gam;
    const float* bet;
    if (id >= V) {
        int oi = id - V;
        oi = max(0, min(oi, N - 1));
        src = ocr + ((size_t)b * (size_t)N + (size_t)oi) * (size_t)H;
        gam = og; bet = ob;
    } else {
        int ci = max(0, min(id, V - 1));
        src = cv + (size_t)ci * (size_t)H;
        gam = cvg; bet = cvb;
    }

    const float4* s4 = (const float4*)src;
    const float4* p4 = (const float4*)(pos + (size_t)t * (size_t)H);
    const float4* t4 = (const float4*)(typ + ((t >= V) ? (size_t)H : (size_t)0));

    // H = 768 -> 192 float4 per row -> 6 per lane (stride-32, coalesced).
    float4 a[6], p[6];
#pragma unroll
    for (int i = 0; i < 6; i++) {
        const int idx = lane + 32 * i;
        a[i] = s4[idx];
        float4 pp = p4[idx];
        float4 tt = t4[idx];
        p[i] = make_float4(pp.x + tt.x, pp.y + tt.y, pp.z + tt.z, pp.w + tt.w);
    }

    float sa = 0.f, ssa = 0.f, sp = 0.f, ssp = 0.f;
#pragma unroll
    for (int i = 0; i < 6; i++) {
        sa  += a[i].x + a[i].y + a[i].z + a[i].w;
        ssa += a[i].x * a[i].x + a[i].y * a[i].y + a[i].z * a[i].z + a[i].w * a[i].w;
        sp  += p[i].x + p[i].y + p[i].z + p[i].w;
        ssp += p[i].x * p[i].x + p[i].y * p[i].y + p[i].z * p[i].z + p[i].w * p[i].w;
    }
    sa = warp_sum(sa); ssa = warp_sum(ssa); sp = warp_sum(sp); ssp = warp_sum(ssp);

    const float invH = 1.0f / (float)H;
    const float mua = sa * invH;
    const float va  = fmaf(-mua, mua, ssa * invH);
    const float mup = sp * invH;
    const float vp  = fmaf(-mup, mup, ssp * invH);
    const float ra  = rsqrtf(va + LN_EPS);
    const float rp  = rsqrtf(vp + LN_EPS);

    // Epilogue straight from registers; gamma/beta streams are L1-resident.
    float4* o4 = (float4*)(out + (size_t)wrow * (size_t)H);
#pragma unroll
    for (int i = 0; i < 6; i++) {
        const int idx = lane + 32 * i;
        const float4 g4  = ((const float4*)gam)[idx];
        const float4 b4  = ((const float4*)bet)[idx];
        const float4 eg4 = ((const float4*)eg)[idx];
        const float4 eb4 = ((const float4*)eb)[idx];
        float4 r;
        r.x = (a[i].x - mua) * ra * g4.x + b4.x + (p[i].x - mup) * rp * eg4.x + eb4.x;
        r.y = (a[i].y - mua) * ra * g4.y + b4.y + (p[i].y - mup) * rp * eg4.y + eb4.y;
        r.z = (a[i].z - mua) * ra * g4.z + b4.z + (p[i].z - mup) * rp * eg4.z + eb4.z;
        r.w = (a[i].w - mua) * ra * g4.w + b4.w + (p[i].w - mup) * rp * eg4.w + eb4.w;
        o4[idx] = r;
    }
}

extern "C" void kernel_launch(void* const* d_in, const int* in_sizes, int n_in,
                              void* d_out, int out_size) {
    const float* cv  = (const float*)d_in[0];
    const float* ocr = (const float*)d_in[1];
    const int*   ids = (const int*)d_in[2];
    const float* cvg = (const float*)d_in[3];
    const float* cvb = (const float*)d_in[4];
    const float* og  = (const float*)d_in[5];
    const float* ob  = (const float*)d_in[6];
    const float* pos = (const float*)d_in[7];
    const float* typ = (const float*)d_in[8];
    const float* eg  = (const float*)d_in[9];
    const float* eb  = (const float*)d_in[10];
    float* out = (float*)d_out;

    const int H  = in_sizes[3];
    const int V  = in_sizes[0] / H;
    const int T  = in_sizes[7] / H;
    const int BT = in_sizes[2];       // B * T
    const int B  = BT / T;
    const int N  = in_sizes[1] / (B * H);

    const int blocks = (BT + WARPS_PER_BLOCK - 1) / WARPS_PER_BLOCK;
    prev_embedding_kernel<<<blocks, WARPS_PER_BLOCK * 32>>>(
        cv, ocr, ids, cvg, cvb, og, ob, pos, typ, eg, eb, out, V, N, T, H, BT);
}